// round 1
// baseline (speedup 1.0000x reference)
#include <cuda_runtime.h>
#include <cstdint>
#include <cstdio>

// ---------------- problem constants ----------------
#define BSZ    2
#define TT     16
#define LSEQ   3136          // TT * 196
#define NROW   6272          // BSZ * LSEQ
#define DM     384
#define DI     768
#define DS     14
#define DTR    24
#define XCOLS  52            // DTR + 2*DS
#define DHID   1536          // 4*DM == 2*DI

// ---------------- scratch (device globals; no allocation allowed) ----------------
__device__ float g_xf [NROW * DI];      // patchified input (6272 x 768)
__device__ float g_h  [NROW * DM];      // residual stream
__device__ float g_ln [NROW * DM];      // layernorm output
__device__ float g_xz [NROW * 2 * DI];  // in_proj output
__device__ float g_xc [NROW * DI];      // conv+silu output
__device__ float g_dbl[NROW * XCOLS];   // x_proj output (dt_r | B | C)
__device__ float g_dt [NROW * DI];      // softplus(dt)
__device__ float g_y  [NROW * DI];      // scan output (gated)
__device__ float g_m1 [NROW * DHID];    // mlp hidden
__device__ float g_pool[32 * DM];       // max-pooled

// ---------------- activations ----------------
__device__ __forceinline__ float softplus_f(float x) {
    return fmaxf(x, 0.f) + log1pf(expf(-fabsf(x)));
}
__device__ __forceinline__ float gelu_f(float x) {
    float x3 = x * x * x;
    float t = tanhf(0.7978845608028654f * (x + 0.044715f * x3));
    return 0.5f * x * (1.f + t);
}

// ---------------- patchify gather ----------------
// xf[n, p, c] = x[n, ch, ph*16+py, pw*16+px];  p=ph*14+pw, c=ch*256+py*16+px
__global__ void gather_patches_k(const float* __restrict__ x, float* __restrict__ xf) {
    int idx = blockIdx.x * blockDim.x + threadIdx.x;
    if (idx >= NROW * DI) return;
    int c   = idx % DI;
    int row = idx / DI;
    int n  = row / 196, p = row % 196;
    int ph = p / 14,   pw = p % 14;
    int ch = c >> 8;
    int rem = c & 255;
    int py = rem >> 4, px = rem & 15;
    xf[idx] = x[((size_t)(n * 3 + ch) * 224 + (ph * 16 + py)) * 224 + (pw * 16 + px)];
}

// ---------------- generic TN SGEMM: C = act(A*W^T + bias) + res ----------------
// A: M x K (row stride lda), W: N x K (row stride ldw), C: M x N (row stride ldc)
// act: 0=none, 1=softplus, 2=gelu
#define BM 128
#define BN 64
#define BK 16
__global__ __launch_bounds__(256) void sgemm_tn(
    const float* __restrict__ A, int lda,
    const float* __restrict__ W, int ldw,
    float* __restrict__ C, int ldc,
    const float* __restrict__ bias,
    const float* __restrict__ res,
    int M, int N, int K, int act)
{
    __shared__ __align__(16) float As[BK][BM];
    __shared__ __align__(16) float Ws[BK][BN];

    int bm0 = blockIdx.y * BM;
    int bn0 = blockIdx.x * BN;
    int tid = threadIdx.x;
    int tn = tid & 15;   // 16 groups * 4 = 64
    int tm = tid >> 4;   // 16 groups * 8 = 128

    float acc[8][4];
#pragma unroll
    for (int i = 0; i < 8; i++)
#pragma unroll
        for (int j = 0; j < 4; j++) acc[i][j] = 0.f;

    for (int k0 = 0; k0 < K; k0 += BK) {
        // A tile: 128x16 = 512 float4, 2 per thread
#pragma unroll
        for (int i = 0; i < 2; i++) {
            int idx = tid + i * 256;
            int r  = idx >> 2;
            int c4 = (idx & 3) * 4;
            int gm = bm0 + r, gk = k0 + c4;
            float4 v = make_float4(0.f, 0.f, 0.f, 0.f);
            if (gm < M && gk < K) v = *(const float4*)(A + (size_t)gm * lda + gk);
            As[c4 + 0][r] = v.x; As[c4 + 1][r] = v.y;
            As[c4 + 2][r] = v.z; As[c4 + 3][r] = v.w;
        }
        // W tile: 64x16 = 256 float4, 1 per thread
        {
            int r  = tid >> 2;
            int c4 = (tid & 3) * 4;
            int gn = bn0 + r, gk = k0 + c4;
            float4 v = make_float4(0.f, 0.f, 0.f, 0.f);
            if (gn < N && gk < K) v = *(const float4*)(W + (size_t)gn * ldw + gk);
            Ws[c4 + 0][r] = v.x; Ws[c4 + 1][r] = v.y;
            Ws[c4 + 2][r] = v.z; Ws[c4 + 3][r] = v.w;
        }
        __syncthreads();

#pragma unroll
        for (int k = 0; k < BK; k++) {
            float4 a0 = *(const float4*)&As[k][tm * 8];
            float4 a1 = *(const float4*)&As[k][tm * 8 + 4];
            float4 w0 = *(const float4*)&Ws[k][tn * 4];
            float a[8] = {a0.x, a0.y, a0.z, a0.w, a1.x, a1.y, a1.z, a1.w};
            float w[4] = {w0.x, w0.y, w0.z, w0.w};
#pragma unroll
            for (int i = 0; i < 8; i++)
#pragma unroll
                for (int j = 0; j < 4; j++)
                    acc[i][j] = fmaf(a[i], w[j], acc[i][j]);
        }
        __syncthreads();
    }

#pragma unroll
    for (int i = 0; i < 8; i++) {
        int gm = bm0 + tm * 8 + i;
        if (gm >= M) continue;
#pragma unroll
        for (int j = 0; j < 4; j++) {
            int gn = bn0 + tn * 4 + j;
            if (gn >= N) continue;
            float v = acc[i][j];
            if (bias) v += bias[gn];
            if (act == 1) v = softplus_f(v);
            else if (act == 2) v = gelu_f(v);
            if (res) v += res[(size_t)gm * ldc + gn];
            C[(size_t)gm * ldc + gn] = v;
        }
    }
}

// ---------------- layernorm (row = 384, 128 threads/row) ----------------
__global__ void layernorm_k(const float* __restrict__ x, const float* __restrict__ g,
                            const float* __restrict__ b, float* __restrict__ out)
{
    int row = blockIdx.x;
    int t = threadIdx.x;
    const float* xr = x + (size_t)row * DM;
    float v0 = xr[t], v1 = xr[t + 128], v2 = xr[t + 256];
    float s  = v0 + v1 + v2;
    float s2 = v0 * v0 + v1 * v1 + v2 * v2;
#pragma unroll
    for (int o = 16; o; o >>= 1) {
        s  += __shfl_xor_sync(0xffffffffu, s,  o);
        s2 += __shfl_xor_sync(0xffffffffu, s2, o);
    }
    __shared__ float ss[4], ss2[4];
    int w = t >> 5;
    if ((t & 31) == 0) { ss[w] = s; ss2[w] = s2; }
    __syncthreads();
    s  = ss[0] + ss[1] + ss[2] + ss[3];
    s2 = ss2[0] + ss2[1] + ss2[2] + ss2[3];
    float mu  = s * (1.f / DM);
    float var = s2 * (1.f / DM) - mu * mu;
    float r = rsqrtf(var + 1e-5f);
    float* orow = out + (size_t)row * DM;
    orow[t]       = (v0 - mu) * r * g[t]       + b[t];
    orow[t + 128] = (v1 - mu) * r * g[t + 128] + b[t + 128];
    orow[t + 256] = (v2 - mu) * r * g[t + 256] + b[t + 256];
}

// ---------------- causal conv1d (width 4) + silu ----------------
__global__ void conv_silu_k(const float* __restrict__ xz, const float* __restrict__ cw,
                            const float* __restrict__ cb, float* __restrict__ xc)
{
    int idx = blockIdx.x * blockDim.x + threadIdx.x;
    if (idx >= NROW * DI) return;
    int e  = idx % DI;
    int bl = idx / DI;
    int b = bl / LSEQ, l = bl % LSEQ;
    float acc = cb[e];
#pragma unroll
    for (int k = 0; k < 4; k++) {
        int ll = l + k - 3;
        if (ll >= 0) acc += cw[e * 4 + k] * xz[((size_t)b * LSEQ + ll) * (2 * DI) + e];
    }
    xc[idx] = acc / (1.f + __expf(-acc));   // silu
}

// ---------------- selective scan (sequential over L, thread per (b,d)) ----------------
// y[b,l,d] = (sum_n h*C + Dp[d]*xc) * silu(z),  h[n] = exp(dt*A[n])*h[n] + (dt*xc)*B[n]
__global__ void scan_k(const float* __restrict__ dt, const float* __restrict__ xc,
                       const float* __restrict__ dbl, const float* __restrict__ xz,
                       const float* __restrict__ A_log, const float* __restrict__ Dp,
                       float* __restrict__ y)
{
    int d = blockIdx.x * blockDim.x + threadIdx.x;
    if (d >= DI) return;
    int b = blockIdx.y;

    float A[DS], h[DS];
#pragma unroll
    for (int n = 0; n < DS; n++) { A[n] = -__expf(A_log[d * DS + n]); h[n] = 0.f; }
    float Dv = Dp[d];

    const float* dtp = dt + (size_t)b * LSEQ * DI + d;
    const float* xcp = xc + (size_t)b * LSEQ * DI + d;
    const float* zp  = xz + (size_t)b * LSEQ * 2 * DI + DI + d;
    const float* blp = dbl + (size_t)b * LSEQ * XCOLS;
    float* yp = y + (size_t)b * LSEQ * DI + d;

    for (int l = 0; l < LSEQ; l++) {
        float dtv = dtp[(size_t)l * DI];
        float xv  = xcp[(size_t)l * DI];
        float w = dtv * xv;
        const float* bc = blp + (size_t)l * XCOLS;
        float ya = 0.f;
#pragma unroll
        for (int n = 0; n < DS; n++) {
            float e = __expf(dtv * A[n]);
            h[n] = e * h[n] + w * bc[DTR + n];
            ya += h[n] * bc[DTR + DS + n];
        }
        float zv = zp[(size_t)l * 2 * DI];
        float sil = zv / (1.f + __expf(-zv));
        yp[(size_t)l * DI] = (ya + Dv * xv) * sil;
    }
}

// ---------------- max-pool over the 196 patches of each (b,t) ----------------
__global__ void pool_k(const float* __restrict__ h, float* __restrict__ pool) {
    int idx = blockIdx.x * blockDim.x + threadIdx.x;
    if (idx >= 32 * DM) return;
    int dm = idx % DM;
    int n  = idx / DM;                 // n = b*16+t; h row index = n*196 + p
    const float* base = h + (size_t)n * 196 * DM + dm;
    float m = -1e30f;
    for (int p = 0; p < 196; p++) m = fmaxf(m, base[(size_t)p * DM]);
    pool[idx] = m;
}

// ---------------- classifier head: out[n,c] = pooled[n] . head_w[c] + head_b[c] ----------------
__global__ void head_k(const float* __restrict__ pool, const float* __restrict__ hw,
                       const float* __restrict__ hb, float* __restrict__ out)
{
    int idx = threadIdx.x;
    if (idx >= 96) return;
    int c = idx % 3, n = idx / 3;
    float acc = hb[c];
    for (int k = 0; k < DM; k++) acc += pool[n * DM + k] * hw[c * DM + k];
    out[idx] = acc;
}

// ---------------- host orchestration ----------------
static void gemm(const float* A, int lda, const float* W, int ldw, float* C, int ldc,
                 const float* bias, const float* res, int M, int N, int K, int act)
{
    dim3 grid((N + BN - 1) / BN, (M + BM - 1) / BM);
    sgemm_tn<<<grid, 256>>>(A, lda, W, ldw, C, ldc, bias, res, M, N, K, act);
}

extern "C" void kernel_launch(void* const* d_in, const int* in_sizes, int n_in,
                              void* d_out, int out_size)
{
    const float* x       = (const float*)d_in[0];
    const float* patch_w = (const float*)d_in[1];
    const float* patch_b = (const float*)d_in[2];
    const float* ln1_g   = (const float*)d_in[3];
    const float* ln1_b   = (const float*)d_in[4];
    const float* in_w    = (const float*)d_in[5];
    const float* conv_w  = (const float*)d_in[6];
    const float* conv_b  = (const float*)d_in[7];
    const float* xproj_w = (const float*)d_in[8];
    const float* dt_w    = (const float*)d_in[9];
    const float* dt_b    = (const float*)d_in[10];
    const float* A_log   = (const float*)d_in[11];
    const float* Dparam  = (const float*)d_in[12];
    const float* out_w   = (const float*)d_in[13];
    const float* ln2_g   = (const float*)d_in[14];
    const float* ln2_b   = (const float*)d_in[15];
    const float* fc1_w   = (const float*)d_in[16];
    const float* fc1_b   = (const float*)d_in[17];
    const float* fc2_w   = (const float*)d_in[18];
    const float* fc2_b   = (const float*)d_in[19];
    const float* head_w  = (const float*)d_in[20];
    const float* head_b  = (const float*)d_in[21];
    float* out = (float*)d_out;

    float *xf, *h, *ln, *xz, *xc, *dbl, *dt, *y, *m1, *pool;
    cudaGetSymbolAddress((void**)&xf,  g_xf);
    cudaGetSymbolAddress((void**)&h,   g_h);
    cudaGetSymbolAddress((void**)&ln,  g_ln);
    cudaGetSymbolAddress((void**)&xz,  g_xz);
    cudaGetSymbolAddress((void**)&xc,  g_xc);
    cudaGetSymbolAddress((void**)&dbl, g_dbl);
    cudaGetSymbolAddress((void**)&dt,  g_dt);
    cudaGetSymbolAddress((void**)&y,   g_y);
    cudaGetSymbolAddress((void**)&m1,  g_m1);
    cudaGetSymbolAddress((void**)&pool, g_pool);

    // patchify + patch embed -> h
    gather_patches_k<<<(NROW * DI + 255) / 256, 256>>>(x, xf);
    gemm(xf, DI, patch_w, DI, h, DM, patch_b, nullptr, NROW, DM, DI, 0);

    for (int i = 0; i < 4; i++) {
        // --- mamba block ---
        layernorm_k<<<NROW, 128>>>(h, ln1_g + i * DM, ln1_b + i * DM, ln);
        gemm(ln, DM, in_w + (size_t)i * 2 * DI * DM, DM, xz, 2 * DI,
             nullptr, nullptr, NROW, 2 * DI, DM, 0);
        conv_silu_k<<<(NROW * DI + 255) / 256, 256>>>(
            xz, conv_w + (size_t)i * DI * 4, conv_b + (size_t)i * DI, xc);
        gemm(xc, DI, xproj_w + (size_t)i * XCOLS * DI, DI, dbl, XCOLS,
             nullptr, nullptr, NROW, XCOLS, DI, 0);
        gemm(dbl, XCOLS, dt_w + (size_t)i * DI * DTR, DTR, dt, DI,
             dt_b + (size_t)i * DI, nullptr, NROW, DI, DTR, 1 /*softplus*/);
        {
            dim3 grid((DI + 127) / 128, BSZ);
            scan_k<<<grid, 128>>>(dt, xc, dbl, xz,
                                  A_log + (size_t)i * DI * DS, Dparam + (size_t)i * DI, y);
        }
        gemm(y, DI, out_w + (size_t)i * DM * DI, DI, h, DM,
             nullptr, h /*residual*/, NROW, DM, DI, 0);

        // --- mlp block ---
        layernorm_k<<<NROW, 128>>>(h, ln2_g + i * DM, ln2_b + i * DM, ln);
        gemm(ln, DM, fc1_w + (size_t)i * DHID * DM, DM, m1, DHID,
             fc1_b + (size_t)i * DHID, nullptr, NROW, DHID, DM, 2 /*gelu*/);
        gemm(m1, DHID, fc2_w + (size_t)i * DM * DHID, DHID, h, DM,
             fc2_b + (size_t)i * DM, h /*residual*/, NROW, DM, DHID, 0);
    }

    pool_k<<<(32 * DM + 127) / 128, 128>>>(h, pool);
    head_k<<<1, 128>>>(pool, head_w, head_b, out);
}

// round 2
// speedup vs baseline: 4.3036x; 4.3036x over previous
#include <cuda_runtime.h>
#include <cstdint>
#include <cstdio>

// ---------------- problem constants ----------------
#define BSZ    2
#define TT     16
#define LSEQ   3136          // TT * 196
#define NROW   6272          // BSZ * LSEQ
#define DM     384
#define DI     768
#define DS     14
#define DTR    24
#define XCOLS  52            // DTR + 2*DS
#define DHID   1536          // 4*DM == 2*DI

// chunked scan
#define NC     56            // number of chunks
#define CS     56            // steps per chunk (NC*CS == LSEQ)

// ---------------- scratch (device globals; no allocation allowed) ----------------
__device__ float g_xf [NROW * DI];      // patchified input (6272 x 768)
__device__ float g_h  [NROW * DM];      // residual stream
__device__ float g_ln [NROW * DM];      // layernorm output
__device__ float g_xz [NROW * 2 * DI];  // in_proj output
__device__ float g_xc [NROW * DI];      // conv+silu output
__device__ float g_dbl[NROW * XCOLS];   // x_proj output (dt_r | B | C)
__device__ float g_dt [NROW * DI];      // softplus(dt)
__device__ float g_y  [NROW * DI];      // scan output (gated)
__device__ float g_m1 [NROW * DHID];    // mlp hidden
__device__ float g_pool[32 * DM];       // max-pooled
// chunk-scan scratch: [b][chunk][d][n]
__device__ float g_P  [BSZ * NC * DI * DS];
__device__ float g_S  [BSZ * NC * DI * DS];
__device__ float g_h0 [BSZ * NC * DI * DS];

// ---------------- activations ----------------
__device__ __forceinline__ float softplus_f(float x) {
    return fmaxf(x, 0.f) + log1pf(expf(-fabsf(x)));
}
__device__ __forceinline__ float gelu_f(float x) {
    float x3 = x * x * x;
    float t = tanhf(0.7978845608028654f * (x + 0.044715f * x3));
    return 0.5f * x * (1.f + t);
}

// ---------------- patchify gather ----------------
__global__ void gather_patches_k(const float* __restrict__ x, float* __restrict__ xf) {
    int idx = blockIdx.x * blockDim.x + threadIdx.x;
    if (idx >= NROW * DI) return;
    int c   = idx % DI;
    int row = idx / DI;
    int n  = row / 196, p = row % 196;
    int ph = p / 14,   pw = p % 14;
    int ch = c >> 8;
    int rem = c & 255;
    int py = rem >> 4, px = rem & 15;
    xf[idx] = x[((size_t)(n * 3 + ch) * 224 + (ph * 16 + py)) * 224 + (pw * 16 + px)];
}

// ---------------- generic TN SGEMM: C = act(A*W^T + bias) + res ----------------
#define BM 128
#define BN 64
#define BK 16
__global__ __launch_bounds__(256) void sgemm_tn(
    const float* __restrict__ A, int lda,
    const float* __restrict__ W, int ldw,
    float* __restrict__ C, int ldc,
    const float* __restrict__ bias,
    const float* __restrict__ res,
    int M, int N, int K, int act)
{
    __shared__ __align__(16) float As[BK][BM];
    __shared__ __align__(16) float Ws[BK][BN];

    int bm0 = blockIdx.y * BM;
    int bn0 = blockIdx.x * BN;
    int tid = threadIdx.x;
    int tn = tid & 15;
    int tm = tid >> 4;

    float acc[8][4];
#pragma unroll
    for (int i = 0; i < 8; i++)
#pragma unroll
        for (int j = 0; j < 4; j++) acc[i][j] = 0.f;

    for (int k0 = 0; k0 < K; k0 += BK) {
#pragma unroll
        for (int i = 0; i < 2; i++) {
            int idx = tid + i * 256;
            int r  = idx >> 2;
            int c4 = (idx & 3) * 4;
            int gm = bm0 + r, gk = k0 + c4;
            float4 v = make_float4(0.f, 0.f, 0.f, 0.f);
            if (gm < M && gk < K) v = *(const float4*)(A + (size_t)gm * lda + gk);
            As[c4 + 0][r] = v.x; As[c4 + 1][r] = v.y;
            As[c4 + 2][r] = v.z; As[c4 + 3][r] = v.w;
        }
        {
            int r  = tid >> 2;
            int c4 = (tid & 3) * 4;
            int gn = bn0 + r, gk = k0 + c4;
            float4 v = make_float4(0.f, 0.f, 0.f, 0.f);
            if (gn < N && gk < K) v = *(const float4*)(W + (size_t)gn * ldw + gk);
            Ws[c4 + 0][r] = v.x; Ws[c4 + 1][r] = v.y;
            Ws[c4 + 2][r] = v.z; Ws[c4 + 3][r] = v.w;
        }
        __syncthreads();

#pragma unroll
        for (int k = 0; k < BK; k++) {
            float4 a0 = *(const float4*)&As[k][tm * 8];
            float4 a1 = *(const float4*)&As[k][tm * 8 + 4];
            float4 w0 = *(const float4*)&Ws[k][tn * 4];
            float a[8] = {a0.x, a0.y, a0.z, a0.w, a1.x, a1.y, a1.z, a1.w};
            float w[4] = {w0.x, w0.y, w0.z, w0.w};
#pragma unroll
            for (int i = 0; i < 8; i++)
#pragma unroll
                for (int j = 0; j < 4; j++)
                    acc[i][j] = fmaf(a[i], w[j], acc[i][j]);
        }
        __syncthreads();
    }

#pragma unroll
    for (int i = 0; i < 8; i++) {
        int gm = bm0 + tm * 8 + i;
        if (gm >= M) continue;
#pragma unroll
        for (int j = 0; j < 4; j++) {
            int gn = bn0 + tn * 4 + j;
            if (gn >= N) continue;
            float v = acc[i][j];
            if (bias) v += bias[gn];
            if (act == 1) v = softplus_f(v);
            else if (act == 2) v = gelu_f(v);
            if (res) v += res[(size_t)gm * ldc + gn];
            C[(size_t)gm * ldc + gn] = v;
        }
    }
}

// ---------------- layernorm (row = 384, 128 threads/row) ----------------
__global__ void layernorm_k(const float* __restrict__ x, const float* __restrict__ g,
                            const float* __restrict__ b, float* __restrict__ out)
{
    int row = blockIdx.x;
    int t = threadIdx.x;
    const float* xr = x + (size_t)row * DM;
    float v0 = xr[t], v1 = xr[t + 128], v2 = xr[t + 256];
    float s  = v0 + v1 + v2;
    float s2 = v0 * v0 + v1 * v1 + v2 * v2;
#pragma unroll
    for (int o = 16; o; o >>= 1) {
        s  += __shfl_xor_sync(0xffffffffu, s,  o);
        s2 += __shfl_xor_sync(0xffffffffu, s2, o);
    }
    __shared__ float ss[4], ss2[4];
    int w = t >> 5;
    if ((t & 31) == 0) { ss[w] = s; ss2[w] = s2; }
    __syncthreads();
    s  = ss[0] + ss[1] + ss[2] + ss[3];
    s2 = ss2[0] + ss2[1] + ss2[2] + ss2[3];
    float mu  = s * (1.f / DM);
    float var = s2 * (1.f / DM) - mu * mu;
    float r = rsqrtf(var + 1e-5f);
    float* orow = out + (size_t)row * DM;
    orow[t]       = (v0 - mu) * r * g[t]       + b[t];
    orow[t + 128] = (v1 - mu) * r * g[t + 128] + b[t + 128];
    orow[t + 256] = (v2 - mu) * r * g[t + 256] + b[t + 256];
}

// ---------------- causal conv1d (width 4) + silu ----------------
__global__ void conv_silu_k(const float* __restrict__ xz, const float* __restrict__ cw,
                            const float* __restrict__ cb, float* __restrict__ xc)
{
    int idx = blockIdx.x * blockDim.x + threadIdx.x;
    if (idx >= NROW * DI) return;
    int e  = idx % DI;
    int bl = idx / DI;
    int b = bl / LSEQ, l = bl % LSEQ;
    float acc = cb[e];
#pragma unroll
    for (int k = 0; k < 4; k++) {
        int ll = l + k - 3;
        if (ll >= 0) acc += cw[e * 4 + k] * xz[((size_t)b * LSEQ + ll) * (2 * DI) + e];
    }
    xc[idx] = acc / (1.f + __expf(-acc));
}

// ================= chunked selective scan =================
// recurrence per (b,d,n): h <- e*h + u,  e = exp(dt*A[n]), u = (dt*xc)*B[l,n]
// chunk composition: h_out = P*h_in + S with P = prod e, S updated S <- e*S + u.

// detect A[n] == (n+1)*A[0] (true for this dataset: A_log = log(1..14));
// if so one __expf per step suffices: e_n = e1^(n+1).
__device__ __forceinline__ bool load_A(const float* __restrict__ A_log, int d, float* A) {
    bool structured = true;
#pragma unroll
    for (int n = 0; n < DS; n++) A[n] = -__expf(A_log[d * DS + n]);
#pragma unroll
    for (int n = 1; n < DS; n++) {
        float want = (n + 1) * A[0];
        structured &= fabsf(A[n] - want) <= 1e-4f * fabsf(want);
    }
    return structured;
}

// pass A: per-chunk (P, S). grid (3, NC, BSZ), block 256 (d = bx*256+tid)
__global__ __launch_bounds__(256) void scan_chunk_partial(
    const float* __restrict__ dt, const float* __restrict__ xc,
    const float* __restrict__ dbl, const float* __restrict__ A_log,
    float* __restrict__ Pout, float* __restrict__ Sout)
{
    __shared__ float sB[CS][DS];
    int d = blockIdx.x * 256 + threadIdx.x;
    int c = blockIdx.y;
    int b = blockIdx.z;
    int l0 = c * CS;

    // stage B rows for this chunk
    for (int i = threadIdx.x; i < CS * DS; i += 256) {
        int s = i / DS, j = i % DS;
        sB[s][j] = dbl[((size_t)(b * LSEQ + l0 + s)) * XCOLS + DTR + j];
    }
    __syncthreads();

    float A[DS];
    bool structured = load_A(A_log, d, A);
    float A0 = A[0];

    float P[DS], S[DS];
#pragma unroll
    for (int n = 0; n < DS; n++) { P[n] = 1.f; S[n] = 0.f; }

    const float* dtp = dt + (size_t)(b * LSEQ + l0) * DI + d;
    const float* xcp = xc + (size_t)(b * LSEQ + l0) * DI + d;

    if (structured) {
        for (int s = 0; s < CS; s++) {
            float dtv = dtp[(size_t)s * DI];
            float xv  = xcp[(size_t)s * DI];
            float w = dtv * xv;
            float e1 = __expf(dtv * A0);
            float ee = 1.f;
#pragma unroll
            for (int n = 0; n < DS; n++) {
                ee *= e1;
                P[n] *= ee;
                S[n] = ee * S[n] + w * sB[s][n];
            }
        }
    } else {
        for (int s = 0; s < CS; s++) {
            float dtv = dtp[(size_t)s * DI];
            float xv  = xcp[(size_t)s * DI];
            float w = dtv * xv;
#pragma unroll
            for (int n = 0; n < DS; n++) {
                float ee = __expf(dtv * A[n]);
                P[n] *= ee;
                S[n] = ee * S[n] + w * sB[s][n];
            }
        }
    }

    size_t base = ((size_t)(b * NC + c) * DI + d) * DS;
#pragma unroll
    for (int n = 0; n < DS; n++) { Pout[base + n] = P[n]; Sout[base + n] = S[n]; }
}

// pass B: sequential fold over chunks. thread per (b,d,n) = 21504
__global__ __launch_bounds__(256) void scan_chunk_seq(
    const float* __restrict__ P, const float* __restrict__ S, float* __restrict__ h0)
{
    int idx = blockIdx.x * blockDim.x + threadIdx.x;
    if (idx >= BSZ * DI * DS) return;
    int b = idx / (DI * DS);
    int r = idx % (DI * DS);
    float h = 0.f;
    for (int c = 0; c < NC; c++) {
        size_t off = (size_t)b * NC * DI * DS + (size_t)c * DI * DS + r;
        h0[off] = h;
        h = P[off] * h + S[off];
    }
}

// pass C: replay chunk with known h0, emit y = (h.C + D*xc) * silu(z)
__global__ __launch_bounds__(256) void scan_chunk_final(
    const float* __restrict__ dt, const float* __restrict__ xc,
    const float* __restrict__ dbl, const float* __restrict__ xz,
    const float* __restrict__ A_log, const float* __restrict__ Dp,
    const float* __restrict__ h0, float* __restrict__ y)
{
    __shared__ float sBC[CS][2 * DS];
    int d = blockIdx.x * 256 + threadIdx.x;
    int c = blockIdx.y;
    int b = blockIdx.z;
    int l0 = c * CS;

    for (int i = threadIdx.x; i < CS * 2 * DS; i += 256) {
        int s = i / (2 * DS), j = i % (2 * DS);
        sBC[s][j] = dbl[((size_t)(b * LSEQ + l0 + s)) * XCOLS + DTR + j];
    }
    __syncthreads();

    float A[DS];
    bool structured = load_A(A_log, d, A);
    float A0 = A[0];
    float Dv = Dp[d];

    float h[DS];
    size_t hbase = ((size_t)(b * NC + c) * DI + d) * DS;
#pragma unroll
    for (int n = 0; n < DS; n++) h[n] = h0[hbase + n];

    const float* dtp = dt + (size_t)(b * LSEQ + l0) * DI + d;
    const float* xcp = xc + (size_t)(b * LSEQ + l0) * DI + d;
    const float* zp  = xz + (size_t)(b * LSEQ + l0) * 2 * DI + DI + d;
    float* yp = y + (size_t)(b * LSEQ + l0) * DI + d;

    if (structured) {
        for (int s = 0; s < CS; s++) {
            float dtv = dtp[(size_t)s * DI];
            float xv  = xcp[(size_t)s * DI];
            float w = dtv * xv;
            float e1 = __expf(dtv * A0);
            float ee = 1.f;
            float ya = 0.f;
#pragma unroll
            for (int n = 0; n < DS; n++) {
                ee *= e1;
                h[n] = ee * h[n] + w * sBC[s][n];
                ya += h[n] * sBC[s][DS + n];
            }
            float zv = zp[(size_t)s * 2 * DI];
            float sil = zv / (1.f + __expf(-zv));
            yp[(size_t)s * DI] = (ya + Dv * xv) * sil;
        }
    } else {
        for (int s = 0; s < CS; s++) {
            float dtv = dtp[(size_t)s * DI];
            float xv  = xcp[(size_t)s * DI];
            float w = dtv * xv;
            float ya = 0.f;
#pragma unroll
            for (int n = 0; n < DS; n++) {
                float ee = __expf(dtv * A[n]);
                h[n] = ee * h[n] + w * sBC[s][n];
                ya += h[n] * sBC[s][DS + n];
            }
            float zv = zp[(size_t)s * 2 * DI];
            float sil = zv / (1.f + __expf(-zv));
            yp[(size_t)s * DI] = (ya + Dv * xv) * sil;
        }
    }
}

// ---------------- max-pool over the 196 patches of each (b,t) ----------------
__global__ void pool_k(const float* __restrict__ h, float* __restrict__ pool) {
    int idx = blockIdx.x * blockDim.x + threadIdx.x;
    if (idx >= 32 * DM) return;
    int dm = idx % DM;
    int n  = idx / DM;
    const float* base = h + (size_t)n * 196 * DM + dm;
    float m = -1e30f;
    for (int p = 0; p < 196; p++) m = fmaxf(m, base[(size_t)p * DM]);
    pool[idx] = m;
}

// ---------------- classifier head ----------------
__global__ void head_k(const float* __restrict__ pool, const float* __restrict__ hw,
                       const float* __restrict__ hb, float* __restrict__ out)
{
    int idx = threadIdx.x;
    if (idx >= 96) return;
    int c = idx % 3, n = idx / 3;
    float acc = hb[c];
    for (int k = 0; k < DM; k++) acc += pool[n * DM + k] * hw[c * DM + k];
    out[idx] = acc;
}

// ---------------- host orchestration ----------------
static void gemm(const float* A, int lda, const float* W, int ldw, float* C, int ldc,
                 const float* bias, const float* res, int M, int N, int K, int act)
{
    dim3 grid((N + BN - 1) / BN, (M + BM - 1) / BM);
    sgemm_tn<<<grid, 256>>>(A, lda, W, ldw, C, ldc, bias, res, M, N, K, act);
}

extern "C" void kernel_launch(void* const* d_in, const int* in_sizes, int n_in,
                              void* d_out, int out_size)
{
    const float* x       = (const float*)d_in[0];
    const float* patch_w = (const float*)d_in[1];
    const float* patch_b = (const float*)d_in[2];
    const float* ln1_g   = (const float*)d_in[3];
    const float* ln1_b   = (const float*)d_in[4];
    const float* in_w    = (const float*)d_in[5];
    const float* conv_w  = (const float*)d_in[6];
    const float* conv_b  = (const float*)d_in[7];
    const float* xproj_w = (const float*)d_in[8];
    const float* dt_w    = (const float*)d_in[9];
    const float* dt_b    = (const float*)d_in[10];
    const float* A_log   = (const float*)d_in[11];
    const float* Dparam  = (const float*)d_in[12];
    const float* out_w   = (const float*)d_in[13];
    const float* ln2_g   = (const float*)d_in[14];
    const float* ln2_b   = (const float*)d_in[15];
    const float* fc1_w   = (const float*)d_in[16];
    const float* fc1_b   = (const float*)d_in[17];
    const float* fc2_w   = (const float*)d_in[18];
    const float* fc2_b   = (const float*)d_in[19];
    const float* head_w  = (const float*)d_in[20];
    const float* head_b  = (const float*)d_in[21];
    float* out = (float*)d_out;

    float *xf, *h, *ln, *xz, *xc, *dbl, *dt, *y, *m1, *pool, *P, *S, *h0;
    cudaGetSymbolAddress((void**)&xf,  g_xf);
    cudaGetSymbolAddress((void**)&h,   g_h);
    cudaGetSymbolAddress((void**)&ln,  g_ln);
    cudaGetSymbolAddress((void**)&xz,  g_xz);
    cudaGetSymbolAddress((void**)&xc,  g_xc);
    cudaGetSymbolAddress((void**)&dbl, g_dbl);
    cudaGetSymbolAddress((void**)&dt,  g_dt);
    cudaGetSymbolAddress((void**)&y,   g_y);
    cudaGetSymbolAddress((void**)&m1,  g_m1);
    cudaGetSymbolAddress((void**)&pool, g_pool);
    cudaGetSymbolAddress((void**)&P,   g_P);
    cudaGetSymbolAddress((void**)&S,   g_S);
    cudaGetSymbolAddress((void**)&h0,  g_h0);

    gather_patches_k<<<(NROW * DI + 255) / 256, 256>>>(x, xf);
    gemm(xf, DI, patch_w, DI, h, DM, patch_b, nullptr, NROW, DM, DI, 0);

    for (int i = 0; i < 4; i++) {
        // --- mamba block ---
        layernorm_k<<<NROW, 128>>>(h, ln1_g + i * DM, ln1_b + i * DM, ln);
        gemm(ln, DM, in_w + (size_t)i * 2 * DI * DM, DM, xz, 2 * DI,
             nullptr, nullptr, NROW, 2 * DI, DM, 0);
        conv_silu_k<<<(NROW * DI + 255) / 256, 256>>>(
            xz, conv_w + (size_t)i * DI * 4, conv_b + (size_t)i * DI, xc);
        gemm(xc, DI, xproj_w + (size_t)i * XCOLS * DI, DI, dbl, XCOLS,
             nullptr, nullptr, NROW, XCOLS, DI, 0);
        gemm(dbl, XCOLS, dt_w + (size_t)i * DI * DTR, DTR, dt, DI,
             dt_b + (size_t)i * DI, nullptr, NROW, DI, DTR, 1 /*softplus*/);

        // --- chunked selective scan ---
        {
            dim3 gA(DI / 256, NC, BSZ);
            scan_chunk_partial<<<gA, 256>>>(dt, xc, dbl,
                                            A_log + (size_t)i * DI * DS, P, S);
            scan_chunk_seq<<<(BSZ * DI * DS + 255) / 256, 256>>>(P, S, h0);
            scan_chunk_final<<<gA, 256>>>(dt, xc, dbl, xz,
                                          A_log + (size_t)i * DI * DS,
                                          Dparam + (size_t)i * DI, h0, y);
        }

        gemm(y, DI, out_w + (size_t)i * DM * DI, DI, h, DM,
             nullptr, h /*residual*/, NROW, DM, DI, 0);

        // --- mlp block ---
        layernorm_k<<<NROW, 128>>>(h, ln2_g + i * DM, ln2_b + i * DM, ln);
        gemm(ln, DM, fc1_w + (size_t)i * DHID * DM, DM, m1, DHID,
             fc1_b + (size_t)i * DHID, nullptr, NROW, DHID, DM, 2 /*gelu*/);
        gemm(m1, DHID, fc2_w + (size_t)i * DM * DHID, DHID, h, DM,
             fc2_b + (size_t)i * DM, h /*residual*/, NROW, DM, DHID, 0);
    }

    pool_k<<<(32 * DM + 127) / 128, 128>>>(h, pool);
    head_k<<<1, 128>>>(pool, head_w, head_b, out);
}